// round 4
// baseline (speedup 1.0000x reference)
#include <cuda_runtime.h>
#include <cstdint>

#define D_   256
#define SP_  64
#define NB_  128
#define NSL_ 65

// ---------------- device scratch ----------------
__device__ float g_wt[3][NSL_][D_][D_];   // [w][slice][i][o]  (B: rows k=i, cols n=o), tf32-rounded
__device__ float g_wot[D_ * D_];
__device__ float g_t1[NB_ * SP_ * D_];
__device__ float g_t2[NB_ * SP_ * D_];
__device__ float g_t3[NB_ * SP_ * D_];
__device__ float g_qh[NB_ * SP_ * D_];
__device__ float g_kh[NB_ * SP_ * D_];
__device__ float g_vh[NB_ * SP_ * D_];
__device__ float g_att[NB_ * SP_ * D_];
__device__ int   g_slice_of_k[225];
__device__ int   g_ps[SP_][40];
__device__ int   g_pd[SP_][40];
__device__ int   g_pcnt[SP_];

__device__ __forceinline__ bool mask_keep(int r, int c) {
    int a = min(r, 14 - r);
    int b = min(c, 14 - c);
    return (a == 7) || (b == 7) || (a >= 5 && b >= 5) || (a == b);
}

__device__ __forceinline__ float* sel_buf(int s) {
    switch (s) {
        case 0: return g_t1;
        case 1: return g_t2;
        case 2: return g_t3;
        case 3: return g_qh;
        case 4: return g_kh;
        case 5: return g_vh;
        default: return g_att;
    }
}

// ---------------- PTX helpers (sm_80+ only) ----------------
__device__ __forceinline__ uint32_t smem_u32(const void* p) {
    uint32_t a;
    asm("{ .reg .u64 t; cvta.to.shared.u64 t, %1; cvt.u32.u64 %0, t; }" : "=r"(a) : "l"(p));
    return a;
}
__device__ __forceinline__ void cp16(uint32_t dst, const void* src) {
    asm volatile("cp.async.cg.shared.global [%0], [%1], 16;" :: "r"(dst), "l"(src));
}
__device__ __forceinline__ void cp_commit() {
    asm volatile("cp.async.commit_group;" ::: "memory");
}
template <int N>
__device__ __forceinline__ void cp_wait() {
    asm volatile("cp.async.wait_group %0;" :: "n"(N) : "memory");
}
__device__ __forceinline__ uint32_t f2tf32(float x) {
    uint32_t r;
    asm("cvt.rna.tf32.f32 %0, %1;" : "=r"(r) : "f"(x));
    return r;
}
__device__ __forceinline__ void mma_tf32(float& c0, float& c1, float& c2, float& c3,
                                         uint32_t a0, uint32_t a1, uint32_t a2, uint32_t a3,
                                         uint32_t b0, uint32_t b1) {
    asm volatile(
        "mma.sync.aligned.m16n8k8.row.col.f32.tf32.tf32.f32 "
        "{%0,%1,%2,%3}, {%4,%5,%6,%7}, {%8,%9}, {%0,%1,%2,%3};"
        : "+f"(c0), "+f"(c1), "+f"(c2), "+f"(c3)
        : "r"(a0), "r"(a1), "r"(a2), "r"(a3), "r"(b0), "r"(b1));
}

// ---------------- setup ----------------
__global__ void setup_tables(const float* __restrict__ wo) {
    int t = threadIdx.x;
    if (t == 0) {
        int cnt = 0;
        for (int kk = 0; kk < 225; kk++)
            g_slice_of_k[kk] = mask_keep(kk / 15, kk % 15) ? cnt++ : -1;
    }
    __syncthreads();
    if (t < 64) {
        int py = t >> 3, px = t & 7;
        int c = 0;
        for (int s = 0; s < 64; s++) {
            int sy = s >> 3, sx = s & 7;
            int sl = g_slice_of_k[(sy - py + 7) * 15 + (sx - px + 7)];
            if (sl >= 0) { g_ps[t][c] = s; g_pd[t][c] = sl; c++; }
        }
        g_pcnt[t] = c;
    }
    for (int idx = t; idx < D_ * D_; idx += blockDim.x) {
        int o = idx >> 8, cc = idx & 255;
        g_wot[cc * D_ + o] = wo[o * D_ + cc];
    }
}

// convert raw inputs to tf32-rounded fp32 staging (g_kh <- k, g_qh <- q, g_vh <- v)
__global__ void cvt_inputs(const float* __restrict__ q,
                           const float* __restrict__ k,
                           const float* __restrict__ v) {
    size_t i = ((size_t)blockIdx.x * blockDim.x + threadIdx.x) * 4;
    float4 a = *(const float4*)(q + i);
    float4 b = *(const float4*)(k + i);
    float4 c = *(const float4*)(v + i);
    a.x = __uint_as_float(f2tf32(a.x)); a.y = __uint_as_float(f2tf32(a.y));
    a.z = __uint_as_float(f2tf32(a.z)); a.w = __uint_as_float(f2tf32(a.w));
    b.x = __uint_as_float(f2tf32(b.x)); b.y = __uint_as_float(f2tf32(b.y));
    b.z = __uint_as_float(f2tf32(b.z)); b.w = __uint_as_float(f2tf32(b.w));
    c.x = __uint_as_float(f2tf32(c.x)); c.y = __uint_as_float(f2tf32(c.y));
    c.z = __uint_as_float(f2tf32(c.z)); c.w = __uint_as_float(f2tf32(c.w));
    *(float4*)(g_qh + i) = a;
    *(float4*)(g_kh + i) = b;
    *(float4*)(g_vh + i) = c;
}

// weight repack: coalesced f4 reads of [o][i][kk]; scattered tf32-rounded writes
__global__ void wt_prep(const float* __restrict__ wk,
                        const float* __restrict__ wq,
                        const float* __restrict__ wv) {
    int w = blockIdx.y;
    const float* src = (w == 0) ? wk : ((w == 1) ? wq : wv);
    size_t base = ((size_t)blockIdx.x * 256 + threadIdx.x) * 4;
    float4 v = *(const float4*)(src + base);
    float vv[4] = {v.x, v.y, v.z, v.w};
#pragma unroll
    for (int e = 0; e < 4; e++) {
        size_t idx = base + e;
        int kk = (int)(idx % 225);
        int oi = (int)(idx / 225);
        int i = oi & 255, o = oi >> 8;
        int sl = g_slice_of_k[kk];
        if (sl >= 0) g_wt[w][sl][i][o] = __uint_as_float(f2tf32(vv[e]));
    }
}

// ---------------- conv as tf32 mma.sync GEMM ----------------
// grid = (2 n-tiles, 64 p, 3 branches). CTA: M=128 x N=128, K streamed in 32-chunks.
// 3-stage cp.async ring, ONE __syncthreads per stage, no cvt in loop, 2 CTAs/SM.
#define AS_STRIDE 36
#define BS_STRIDE 136
#define A_STG (128 * AS_STRIDE)
#define B_STG (32 * BS_STRIDE)
#define NST 3
#define SMEM_FLOATS (NST * (A_STG + B_STG))
#define SMEM_BYTES (SMEM_FLOATS * 4)          /* 107520 B */

__global__ void __launch_bounds__(256, 2) conv_mma(
    int xsa, int xsb, int xsc,
    int wa, int wb, int wc,
    const float* ba, const float* bb, const float* bc,
    int ya, int yb, int yc, int doRelu)
{
    extern __shared__ float smem[];
    float* As = smem;                          // [NST][128][36]
    float* Bs = smem + NST * A_STG;            // [NST][32][136]
    __shared__ int s_ps[40], s_pd[40];

    int tid = threadIdx.x, wid = tid >> 5, lane = tid & 31;
    int o0 = blockIdx.x << 7;
    int p  = blockIdx.y;
    int br = blockIdx.z;

    const float* X; int widx; const float* bias; int ysel;
    if (br == 0)      { X = sel_buf(xsa); widx = wa; bias = ba; ysel = ya; }
    else if (br == 1) { X = sel_buf(xsb); widx = wb; bias = bb; ysel = yb; }
    else              { X = sel_buf(xsc); widx = wc; bias = bc; ysel = yc; }
    float* Y = sel_buf(ysel);
    const float* WT = &g_wt[widx][0][0][0];

    int cnt = g_pcnt[p];
    if (tid < cnt) { s_ps[tid] = g_ps[p][tid]; s_pd[tid] = g_pd[p][tid]; }
    __syncthreads();
    int NC = cnt * 8;

    int arow = tid >> 1;
    int ac4  = (tid & 1) * 4;

    uint32_t as_base = smem_u32(As);
    uint32_t bs_base = smem_u32(Bs);

    int wm = wid & 1, wn = wid >> 1;
    int g = lane >> 2, t = lane & 3;

    float acc[4][4][4];
#pragma unroll
    for (int mi = 0; mi < 4; mi++)
#pragma unroll
        for (int ni = 0; ni < 4; ni++)
#pragma unroll
            for (int e = 0; e < 4; e++) acc[mi][ni][e] = 0.f;

    auto issue = [&](int n) {
        int buf = n % NST;
        int si = n >> 3;
        int s  = s_ps[si];
        int sl = s_pd[si];
        int i0 = (n & 7) * 32;
        const float* asrc = X + ((size_t)(arow * SP_ + s) * D_ + i0);
        uint32_t adst = as_base + (uint32_t)(buf * A_STG + arow * AS_STRIDE) * 4;
#pragma unroll
        for (int j = 0; j < 4; j++)
            cp16(adst + (uint32_t)(ac4 + j) * 16, asrc + (ac4 + j) * 4);
        const float* wbase = WT + (size_t)sl * (D_ * D_) + (size_t)i0 * D_ + o0;
#pragma unroll
        for (int j = 0; j < 4; j++) {
            int idx = tid + (j << 8);
            int r = idx >> 5, c4 = idx & 31;
            cp16(bs_base + (uint32_t)(buf * B_STG + r * BS_STRIDE + c4 * 4) * 4,
                 wbase + (size_t)r * D_ + c4 * 4);
        }
        cp_commit();
    };

    issue(0);
    if (NC > 1) issue(1);

#pragma unroll 1
    for (int n = 0; n < NC; n++) {
        if (n + 1 < NC) cp_wait<1>(); else cp_wait<0>();
        __syncthreads();
        if (n + 2 < NC) issue(n + 2);

        const float* Ab = As + (n % NST) * A_STG;
        const float* Bb = Bs + (n % NST) * B_STG;
#pragma unroll
        for (int kk = 0; kk < 4; kk++) {
            int k0 = kk * 8;
            uint32_t af[4][4];
#pragma unroll
            for (int mi = 0; mi < 4; mi++) {
                int m = wm * 64 + mi * 16;
                const float* ap = Ab + (size_t)(m + g) * AS_STRIDE + k0 + t;
                af[mi][0] = __float_as_uint(ap[0]);
                af[mi][1] = __float_as_uint(ap[8 * AS_STRIDE]);
                af[mi][2] = __float_as_uint(ap[4]);
                af[mi][3] = __float_as_uint(ap[8 * AS_STRIDE + 4]);
            }
            uint32_t bf[4][2];
#pragma unroll
            for (int ni = 0; ni < 4; ni++) {
                int nn = wn * 32 + ni * 8;
                const float* bp = Bb + (size_t)(k0 + t) * BS_STRIDE + nn + g;
                bf[ni][0] = __float_as_uint(bp[0]);
                bf[ni][1] = __float_as_uint(bp[4 * BS_STRIDE]);
            }
#pragma unroll
            for (int mi = 0; mi < 4; mi++)
#pragma unroll
                for (int ni = 0; ni < 4; ni++)
                    mma_tf32(acc[mi][ni][0], acc[mi][ni][1], acc[mi][ni][2], acc[mi][ni][3],
                             af[mi][0], af[mi][1], af[mi][2], af[mi][3],
                             bf[ni][0], bf[ni][1]);
        }
    }

    // epilogue: c0=(g,2t) c1=(g,2t+1) c2=(g+8,2t) c3=(g+8,2t+1)
#pragma unroll
    for (int mi = 0; mi < 4; mi++) {
#pragma unroll
        for (int ni = 0; ni < 4; ni++) {
            int m  = wm * 64 + mi * 16 + g;
            int nn = o0 + wn * 32 + ni * 8 + 2 * t;
            float b0 = bias[nn], b1 = bias[nn + 1];
            float v0 = acc[mi][ni][0] + b0, v1 = acc[mi][ni][1] + b1;
            float v2 = acc[mi][ni][2] + b0, v3 = acc[mi][ni][3] + b1;
            if (doRelu) {
                v0 = __uint_as_float(f2tf32(fmaxf(v0, 0.f)));
                v1 = __uint_as_float(f2tf32(fmaxf(v1, 0.f)));
                v2 = __uint_as_float(f2tf32(fmaxf(v2, 0.f)));
                v3 = __uint_as_float(f2tf32(fmaxf(v3, 0.f)));
            }
            float* y0 = Y + ((size_t)(m * SP_ + p) * D_ + nn);
            float* y1 = Y + ((size_t)((m + 8) * SP_ + p) * D_ + nn);
            *(float2*)y0 = make_float2(v0, v1);
            *(float2*)y1 = make_float2(v2, v3);
        }
    }
}

// ---------------- attention ----------------
__global__ void __launch_bounds__(256) attn_kernel() {
    __shared__ float sq[64][33];
    __shared__ float sk[64][33];
    __shared__ float sv[64][33];
    __shared__ float sc[64][64];
    int b = blockIdx.x >> 3, h = blockIdx.x & 7;
    int tid = threadIdx.x;
    const float* qb = g_qh + (size_t)b * (SP_ * D_) + h * 32;
    const float* kb = g_kh + (size_t)b * (SP_ * D_) + h * 32;
    const float* vb = g_vh + (size_t)b * (SP_ * D_) + h * 32;
#pragma unroll
    for (int e = 0; e < 8; e++) {
        int idx = tid + e * 256;
        int pp = idx >> 5, dk = idx & 31;
        sq[pp][dk] = qb[pp * D_ + dk];
        sk[pp][dk] = kb[pp * D_ + dk];
        sv[pp][dk] = vb[pp * D_ + dk];
    }
    __syncthreads();
    int lane = tid & 31, w = tid >> 5;
    const float scale = 0.17677669529663687f;
#pragma unroll 1
    for (int r = 0; r < 8; r++) {
        int i = w * 8 + r;
        float a0 = 0.f, a1 = 0.f;
#pragma unroll
        for (int dk = 0; dk < 32; dk++) {
            float qv = sq[i][dk];
            a0 = fmaf(qv, sk[lane][dk], a0);
            a1 = fmaf(qv, sk[lane + 32][dk], a1);
        }
        a0 *= scale; a1 *= scale;
        float mx = fmaxf(a0, a1);
#pragma unroll
        for (int off = 16; off; off >>= 1) mx = fmaxf(mx, __shfl_xor_sync(0xffffffffu, mx, off));
        float e0 = __expf(a0 - mx), e1 = __expf(a1 - mx);
        float sm = e0 + e1;
#pragma unroll
        for (int off = 16; off; off >>= 1) sm += __shfl_xor_sync(0xffffffffu, sm, off);
        float inv = 1.0f / sm;
        sc[i][lane] = e0 * inv;
        sc[i][lane + 32] = e1 * inv;
    }
    __syncthreads();
    float o[8];
#pragma unroll
    for (int r = 0; r < 8; r++) o[r] = 0.f;
#pragma unroll 1
    for (int j = 0; j < 64; j++) {
        float vv = sv[j][lane];
#pragma unroll
        for (int r = 0; r < 8; r++) o[r] = fmaf(sc[w * 8 + r][j], vv, o[r]);
    }
    float* ob = g_att + (size_t)b * (SP_ * D_) + h * 32 + lane;
#pragma unroll
    for (int r = 0; r < 8; r++) ob[(size_t)(w * 8 + r) * D_] = o[r];
}

// ---------------- output projection ----------------
__global__ void __launch_bounds__(256) out_gemm(const float* __restrict__ bo, float* __restrict__ Y) {
    __shared__ float As2[8][132];
    __shared__ float Bs2[8][68];
    int o0   = blockIdx.x << 6;
    int row0 = blockIdx.y << 7;
    int tid = threadIdx.x;
    int tx = tid & 15, ty = tid >> 4;
    float acc[8][4];
#pragma unroll
    for (int r = 0; r < 8; r++)
#pragma unroll
        for (int c = 0; c < 4; c++) acc[r][c] = 0.f;
    int am = tid >> 1, akb = (tid & 1) * 4;
    const float* A = g_att + (size_t)(row0 + am) * D_ + akb;
#pragma unroll 1
    for (int i0 = 0; i0 < D_; i0 += 8) {
        float4 va = *(const float4*)(A + i0);
        As2[akb + 0][am] = va.x; As2[akb + 1][am] = va.y;
        As2[akb + 2][am] = va.z; As2[akb + 3][am] = va.w;
#pragma unroll
        for (int e = 0; e < 2; e++) {
            int idx = tid + e * 256;
            int kq = idx >> 6, nn = idx & 63;
            Bs2[kq][nn] = g_wot[(size_t)(i0 + kq) * D_ + o0 + nn];
        }
        __syncthreads();
#pragma unroll
        for (int kk = 0; kk < 8; kk++) {
            float a[8], b4[4];
            *(float4*)(a)     = *(const float4*)&As2[kk][ty * 4];
            *(float4*)(a + 4) = *(const float4*)&As2[kk][64 + ty * 4];
            *(float4*)(b4)    = *(const float4*)&Bs2[kk][tx * 4];
#pragma unroll
            for (int r = 0; r < 8; r++)
#pragma unroll
                for (int c = 0; c < 4; c++)
                    acc[r][c] = fmaf(a[r], b4[c], acc[r][c]);
        }
        __syncthreads();
    }
#pragma unroll
    for (int r = 0; r < 8; r++) {
        int m = (r < 4) ? (ty * 4 + r) : (64 + ty * 4 + r - 4);
        float* yrow = Y + (size_t)(row0 + m) * D_ + o0;
#pragma unroll
        for (int c = 0; c < 4; c++) {
            int nn = tx * 4 + c;
            yrow[nn] = acc[r][c] + bo[o0 + nn];
        }
    }
}

// ---------------- launch ----------------
extern "C" void kernel_launch(void* const* d_in, const int* in_sizes, int n_in,
                              void* d_out, int out_size) {
    (void)in_sizes; (void)n_in; (void)out_size;
    const float* q  = (const float*)d_in[0];
    const float* k  = (const float*)d_in[1];
    const float* v  = (const float*)d_in[2];
    const float* wk = (const float*)d_in[3];
    const float* bk = (const float*)d_in[4];
    const float* wq = (const float*)d_in[5];
    const float* bq = (const float*)d_in[6];
    const float* wv = (const float*)d_in[7];
    const float* bv = (const float*)d_in[8];
    const float* wo = (const float*)d_in[9];
    const float* bo = (const float*)d_in[10];
    float* out = (float*)d_out;

    static int smem_set = 0;
    if (!smem_set) {
        cudaFuncSetAttribute(conv_mma, cudaFuncAttributeMaxDynamicSharedMemorySize, SMEM_BYTES);
        smem_set = 1;
    }

    setup_tables<<<1, 256>>>(wo);
    cvt_inputs<<<(NB_ * SP_ * D_) / (256 * 4), 256>>>(q, k, v);
    wt_prep<<<dim3(14400, 3), 256>>>(wk, wq, wv);

    dim3 cgrid(2, 64, 3);
    // Phase 1: t1=relu(conv(k',wk)+bk), t2=relu(conv(q',wq)+bq), t3=relu(conv(v',wv)+bv)
    // (k' = tf32(k) staged in g_kh, q' in g_qh, v' in g_vh)
    conv_mma<<<cgrid, 256, SMEM_BYTES>>>(4, 3, 5,
                                         0, 1, 2,
                                         bk, bq, bv,
                                         0, 1, 2, 1);
    // Phase 2: kh=conv(t1,wk)+bk, qh=conv(t2,wk)+bk (weight-sharing quirk), vh=conv(t3,wv)+bv
    conv_mma<<<cgrid, 256, SMEM_BYTES>>>(0, 1, 2,
                                         0, 0, 2,
                                         bk, bk, bv,
                                         4, 3, 5, 0);

    attn_kernel<<<NB_ * 8, 256>>>();
    out_gemm<<<dim3(4, 64), 256>>>(bo, out);
}

// round 5
// speedup vs baseline: 1.9300x; 1.9300x over previous
#include <cuda_runtime.h>
#include <cuda_fp16.h>
#include <cstdint>

#define D_   256
#define SP_  64
#define NB_  128
#define NSL_ 65

// ---------------- device scratch ----------------
__device__ __half g_wth[3][NSL_][D_][D_]; // [w][slice][o][i]  fp16 weights (B operand, n-major rows)
__device__ __half g_xh[3][NB_ * SP_ * D_]; // staged inputs: [0]=q, [1]=k, [2]=v (half)
__device__ __half g_th[3][NB_ * SP_ * D_]; // branch hidden t1..t3 (half)
__device__ float g_wot[D_ * D_];
__device__ float g_qh[NB_ * SP_ * D_];
__device__ float g_kh[NB_ * SP_ * D_];
__device__ float g_vh[NB_ * SP_ * D_];
__device__ float g_att[NB_ * SP_ * D_];
__device__ int   g_slice_of_k[225];
__device__ int   g_ps[SP_][40];
__device__ int   g_pd[SP_][40];
__device__ int   g_pcnt[SP_];

__device__ __forceinline__ bool mask_keep(int r, int c) {
    int a = min(r, 14 - r);
    int b = min(c, 14 - c);
    return (a == 7) || (b == 7) || (a >= 5 && b >= 5) || (a == b);
}

__device__ __forceinline__ float* fsel(int s) {
    switch (s) {
        case 0: return g_qh;
        case 1: return g_kh;
        default: return g_vh;
    }
}

// ---------------- PTX helpers ----------------
__device__ __forceinline__ uint32_t smem_u32(const void* p) {
    uint32_t a;
    asm("{ .reg .u64 t; cvta.to.shared.u64 t, %1; cvt.u32.u64 %0, t; }" : "=r"(a) : "l"(p));
    return a;
}
__device__ __forceinline__ void cp16(uint32_t dst, const void* src) {
    asm volatile("cp.async.cg.shared.global [%0], [%1], 16;" :: "r"(dst), "l"(src));
}
__device__ __forceinline__ void cp_commit() {
    asm volatile("cp.async.commit_group;" ::: "memory");
}
template <int N>
__device__ __forceinline__ void cp_wait() {
    asm volatile("cp.async.wait_group %0;" :: "n"(N) : "memory");
}
__device__ __forceinline__ void mma_f16(float& c0, float& c1, float& c2, float& c3,
                                        uint32_t a0, uint32_t a1, uint32_t a2, uint32_t a3,
                                        uint32_t b0, uint32_t b1) {
    asm volatile(
        "mma.sync.aligned.m16n8k16.row.col.f32.f16.f16.f32 "
        "{%0,%1,%2,%3}, {%4,%5,%6,%7}, {%8,%9}, {%0,%1,%2,%3};"
        : "+f"(c0), "+f"(c1), "+f"(c2), "+f"(c3)
        : "r"(a0), "r"(a1), "r"(a2), "r"(a3), "r"(b0), "r"(b1));
}

// ---------------- setup ----------------
__global__ void setup_tables(const float* __restrict__ wo) {
    int t = threadIdx.x;
    if (t == 0) {
        int cnt = 0;
        for (int kk = 0; kk < 225; kk++)
            g_slice_of_k[kk] = mask_keep(kk / 15, kk % 15) ? cnt++ : -1;
    }
    __syncthreads();
    if (t < 64) {
        int py = t >> 3, px = t & 7;
        int c = 0;
        for (int s = 0; s < 64; s++) {
            int sy = s >> 3, sx = s & 7;
            int sl = g_slice_of_k[(sy - py + 7) * 15 + (sx - px + 7)];
            if (sl >= 0) { g_ps[t][c] = s; g_pd[t][c] = sl; c++; }
        }
        g_pcnt[t] = c;
    }
    for (int idx = t; idx < D_ * D_; idx += blockDim.x) {
        int o = idx >> 8, cc = idx & 255;
        g_wot[cc * D_ + o] = wo[o * D_ + cc];
    }
}

// inputs -> half staging
__global__ void cvt_inputs(const float* __restrict__ q,
                           const float* __restrict__ k,
                           const float* __restrict__ v) {
    size_t i = ((size_t)blockIdx.x * blockDim.x + threadIdx.x) * 4;
    float4 a = *(const float4*)(q + i);
    float4 b = *(const float4*)(k + i);
    float4 c = *(const float4*)(v + i);
    *(__half2*)(&g_xh[0][i])     = __floats2half2_rn(a.x, a.y);
    *(__half2*)(&g_xh[0][i + 2]) = __floats2half2_rn(a.z, a.w);
    *(__half2*)(&g_xh[1][i])     = __floats2half2_rn(b.x, b.y);
    *(__half2*)(&g_xh[1][i + 2]) = __floats2half2_rn(b.z, b.w);
    *(__half2*)(&g_xh[2][i])     = __floats2half2_rn(c.x, c.y);
    *(__half2*)(&g_xh[2][i + 2]) = __floats2half2_rn(c.z, c.w);
}

// weight repack: coalesced f4 reads of [o][i][kk]; scattered half writes -> [sl][o][i]
__global__ void wt_prep(const float* __restrict__ wk,
                        const float* __restrict__ wq,
                        const float* __restrict__ wv) {
    int w = blockIdx.y;
    const float* src = (w == 0) ? wk : ((w == 1) ? wq : wv);
    size_t base = ((size_t)blockIdx.x * 256 + threadIdx.x) * 4;
    float4 v = *(const float4*)(src + base);
    float vv[4] = {v.x, v.y, v.z, v.w};
#pragma unroll
    for (int e = 0; e < 4; e++) {
        size_t idx = base + e;
        int kk = (int)(idx % 225);
        int oi = (int)(idx / 225);
        int i = oi & 255, o = oi >> 8;
        int sl = g_slice_of_k[kk];
        if (sl >= 0) g_wth[w][sl][o][i] = __float2half_rn(vv[e]);
    }
}

// ---------------- conv as fp16 mma.sync GEMM ----------------
// grid = (2 n-tiles, 64 p, 3 branches). CTA: M=128(batch) x N=128(o), K streamed
// in 32-chunks over active s. 4-stage cp.async ring, 2 CTAs/SM.
#define PADK 40
#define A_STG_H (128 * PADK)     /* halves per A stage */
#define B_STG_H (128 * PADK)
#define NST 4
#define SMEM_BYTES (NST * (A_STG_H + B_STG_H) * 2)   /* 81920 */

__global__ void __launch_bounds__(256, 2) conv_mma(
    int xa, int xb, int xc,           // 0-2: g_xh, 3-5: g_th
    int wa, int wb, int wc,
    const float* ba, const float* bb, const float* bc,
    int ya, int yb, int yc,           // outHalf: g_th idx; else fsel idx
    int outHalf)                      // also = doRelu
{
    extern __shared__ __half smh[];
    __half* As = smh;                           // [NST][128][PADK]
    __half* Bs = smh + NST * A_STG_H;
    __shared__ int s_ps[40], s_pd[40];

    int tid = threadIdx.x, wid = tid >> 5, lane = tid & 31;
    int o0 = blockIdx.x << 7;
    int p  = blockIdx.y;
    int br = blockIdx.z;

    int xsel, widx, ysel;
    const float* bias;
    if (br == 0)      { xsel = xa; widx = wa; bias = ba; ysel = ya; }
    else if (br == 1) { xsel = xb; widx = wb; bias = bb; ysel = yb; }
    else              { xsel = xc; widx = wc; bias = bc; ysel = yc; }
    const __half* X = (xsel < 3) ? g_xh[xsel] : g_th[xsel - 3];
    const __half* WTh = &g_wth[widx][0][0][0];

    int cnt = g_pcnt[p];
    if (tid < cnt) { s_ps[tid] = g_ps[p][tid]; s_pd[tid] = g_pd[p][tid]; }
    __syncthreads();
    int NC = cnt * 8;

    uint32_t as_base = smem_u32(As);
    uint32_t bs_base = smem_u32(Bs);

    int wm = wid & 1, wn = wid >> 1;
    int g = lane >> 2, t = lane & 3;

    float acc[4][4][4];
#pragma unroll
    for (int mi = 0; mi < 4; mi++)
#pragma unroll
        for (int ni = 0; ni < 4; ni++)
#pragma unroll
            for (int e = 0; e < 4; e++) acc[mi][ni][e] = 0.f;

    auto issue = [&](int n) {
        int buf = n & 3;
        int si = n >> 3;
        int s  = s_ps[si];
        int sl = s_pd[si];
        int i0 = (n & 7) * 32;
#pragma unroll
        for (int e = 0; e < 2; e++) {
            int c = tid + (e << 8);
            int row = c >> 2, part = c & 3;
            cp16(as_base + (uint32_t)(buf * A_STG_H + row * PADK) * 2 + part * 16,
                 X + ((size_t)(row * SP_ + s) * D_ + i0 + part * 8));
        }
#pragma unroll
        for (int e = 0; e < 2; e++) {
            int c = tid + (e << 8);
            int row = c >> 2, part = c & 3;
            cp16(bs_base + (uint32_t)(buf * B_STG_H + row * PADK) * 2 + part * 16,
                 WTh + ((size_t)sl * (D_ * D_) + (size_t)(o0 + row) * D_ + i0 + part * 8));
        }
        cp_commit();
    };

    issue(0); issue(1); issue(2);

#pragma unroll 1
    for (int n = 0; n < NC; n++) {
        if (n + 3 <= NC)      cp_wait<2>();
        else if (n + 2 == NC) cp_wait<1>();
        else                  cp_wait<0>();
        __syncthreads();
        if (n + 3 < NC) issue(n + 3);

        const __half* Ab = As + (n & 3) * A_STG_H;
        const __half* Bb = Bs + (n & 3) * B_STG_H;
#pragma unroll
        for (int ks = 0; ks < 2; ks++) {
            int k0 = ks * 16;
            uint32_t af[4][4];
#pragma unroll
            for (int mi = 0; mi < 4; mi++) {
                const __half* ap = Ab + (size_t)(wm * 64 + mi * 16 + g) * PADK + k0 + 2 * t;
                af[mi][0] = *(const uint32_t*)ap;
                af[mi][1] = *(const uint32_t*)(ap + 8 * PADK);
                af[mi][2] = *(const uint32_t*)(ap + 8);
                af[mi][3] = *(const uint32_t*)(ap + 8 * PADK + 8);
            }
            uint32_t bf[4][2];
#pragma unroll
            for (int ni = 0; ni < 4; ni++) {
                const __half* bp = Bb + (size_t)(wn * 32 + ni * 8 + g) * PADK + k0 + 2 * t;
                bf[ni][0] = *(const uint32_t*)bp;
                bf[ni][1] = *(const uint32_t*)(bp + 8);
            }
#pragma unroll
            for (int mi = 0; mi < 4; mi++)
#pragma unroll
                for (int ni = 0; ni < 4; ni++)
                    mma_f16(acc[mi][ni][0], acc[mi][ni][1], acc[mi][ni][2], acc[mi][ni][3],
                            af[mi][0], af[mi][1], af[mi][2], af[mi][3],
                            bf[ni][0], bf[ni][1]);
        }
    }

    // epilogue: c0=(g,2t) c1=(g,2t+1) c2=(g+8,2t) c3=(g+8,2t+1)
    if (outHalf) {
        __half* Y = g_th[ysel];
#pragma unroll
        for (int mi = 0; mi < 4; mi++) {
#pragma unroll
            for (int ni = 0; ni < 4; ni++) {
                int m  = wm * 64 + mi * 16 + g;
                int nn = o0 + wn * 32 + ni * 8 + 2 * t;
                float b0 = bias[nn], b1 = bias[nn + 1];
                float v0 = fmaxf(acc[mi][ni][0] + b0, 0.f);
                float v1 = fmaxf(acc[mi][ni][1] + b1, 0.f);
                float v2 = fmaxf(acc[mi][ni][2] + b0, 0.f);
                float v3 = fmaxf(acc[mi][ni][3] + b1, 0.f);
                *(__half2*)(Y + ((size_t)(m * SP_ + p) * D_ + nn))       = __floats2half2_rn(v0, v1);
                *(__half2*)(Y + ((size_t)((m + 8) * SP_ + p) * D_ + nn)) = __floats2half2_rn(v2, v3);
            }
        }
    } else {
        float* Y = fsel(ysel);
#pragma unroll
        for (int mi = 0; mi < 4; mi++) {
#pragma unroll
            for (int ni = 0; ni < 4; ni++) {
                int m  = wm * 64 + mi * 16 + g;
                int nn = o0 + wn * 32 + ni * 8 + 2 * t;
                float b0 = bias[nn], b1 = bias[nn + 1];
                *(float2*)(Y + ((size_t)(m * SP_ + p) * D_ + nn)) =
                    make_float2(acc[mi][ni][0] + b0, acc[mi][ni][1] + b1);
                *(float2*)(Y + ((size_t)((m + 8) * SP_ + p) * D_ + nn)) =
                    make_float2(acc[mi][ni][2] + b0, acc[mi][ni][3] + b1);
            }
        }
    }
}

// ---------------- attention ----------------
__global__ void __launch_bounds__(256) attn_kernel() {
    __shared__ float sq[64][33];
    __shared__ float sk[64][33];
    __shared__ float sv[64][33];
    __shared__ float sc[64][64];
    int b = blockIdx.x >> 3, h = blockIdx.x & 7;
    int tid = threadIdx.x;
    const float* qb = g_qh + (size_t)b * (SP_ * D_) + h * 32;
    const float* kb = g_kh + (size_t)b * (SP_ * D_) + h * 32;
    const float* vb = g_vh + (size_t)b * (SP_ * D_) + h * 32;
#pragma unroll
    for (int e = 0; e < 8; e++) {
        int idx = tid + e * 256;
        int pp = idx >> 5, dk = idx & 31;
        sq[pp][dk] = qb[pp * D_ + dk];
        sk[pp][dk] = kb[pp * D_ + dk];
        sv[pp][dk] = vb[pp * D_ + dk];
    }
    __syncthreads();
    int lane = tid & 31, w = tid >> 5;
    const float scale = 0.17677669529663687f;
#pragma unroll 1
    for (int r = 0; r < 8; r++) {
        int i = w * 8 + r;
        float a0 = 0.f, a1 = 0.f;
#pragma unroll
        for (int dk = 0; dk < 32; dk++) {
            float qv = sq[i][dk];
            a0 = fmaf(qv, sk[lane][dk], a0);
            a1 = fmaf(qv, sk[lane + 32][dk], a1);
        }
        a0 *= scale; a1 *= scale;
        float mx = fmaxf(a0, a1);
#pragma unroll
        for (int off = 16; off; off >>= 1) mx = fmaxf(mx, __shfl_xor_sync(0xffffffffu, mx, off));
        float e0 = __expf(a0 - mx), e1 = __expf(a1 - mx);
        float sm = e0 + e1;
#pragma unroll
        for (int off = 16; off; off >>= 1) sm += __shfl_xor_sync(0xffffffffu, sm, off);
        float inv = 1.0f / sm;
        sc[i][lane] = e0 * inv;
        sc[i][lane + 32] = e1 * inv;
    }
    __syncthreads();
    float o[8];
#pragma unroll
    for (int r = 0; r < 8; r++) o[r] = 0.f;
#pragma unroll 1
    for (int j = 0; j < 64; j++) {
        float vv = sv[j][lane];
#pragma unroll
        for (int r = 0; r < 8; r++) o[r] = fmaf(sc[w * 8 + r][j], vv, o[r]);
    }
    float* ob = g_att + (size_t)b * (SP_ * D_) + h * 32 + lane;
#pragma unroll
    for (int r = 0; r < 8; r++) ob[(size_t)(w * 8 + r) * D_] = o[r];
}

// ---------------- output projection ----------------
__global__ void __launch_bounds__(256) out_gemm(const float* __restrict__ bo, float* __restrict__ Y) {
    __shared__ float As2[8][132];
    __shared__ float Bs2[8][68];
    int o0   = blockIdx.x << 6;
    int row0 = blockIdx.y << 7;
    int tid = threadIdx.x;
    int tx = tid & 15, ty = tid >> 4;
    float acc[8][4];
#pragma unroll
    for (int r = 0; r < 8; r++)
#pragma unroll
        for (int c = 0; c < 4; c++) acc[r][c] = 0.f;
    int am = tid >> 1, akb = (tid & 1) * 4;
    const float* A = g_att + (size_t)(row0 + am) * D_ + akb;
#pragma unroll 1
    for (int i0 = 0; i0 < D_; i0 += 8) {
        float4 va = *(const float4*)(A + i0);
        As2[akb + 0][am] = va.x; As2[akb + 1][am] = va.y;
        As2[akb + 2][am] = va.z; As2[akb + 3][am] = va.w;
#pragma unroll
        for (int e = 0; e < 2; e++) {
            int idx = tid + e * 256;
            int kq = idx >> 6, nn = idx & 63;
            Bs2[kq][nn] = g_wot[(size_t)(i0 + kq) * D_ + o0 + nn];
        }
        __syncthreads();
#pragma unroll
        for (int kk = 0; kk < 8; kk++) {
            float a[8], b4[4];
            *(float4*)(a)     = *(const float4*)&As2[kk][ty * 4];
            *(float4*)(a + 4) = *(const float4*)&As2[kk][64 + ty * 4];
            *(float4*)(b4)    = *(const float4*)&Bs2[kk][tx * 4];
#pragma unroll
            for (int r = 0; r < 8; r++)
#pragma unroll
                for (int c = 0; c < 4; c++)
                    acc[r][c] = fmaf(a[r], b4[c], acc[r][c]);
        }
        __syncthreads();
    }
#pragma unroll
    for (int r = 0; r < 8; r++) {
        int m = (r < 4) ? (ty * 4 + r) : (64 + ty * 4 + r - 4);
        float* yrow = Y + (size_t)(row0 + m) * D_ + o0;
#pragma unroll
        for (int c = 0; c < 4; c++) {
            int nn = tx * 4 + c;
            yrow[nn] = acc[r][c] + bo[o0 + nn];
        }
    }
}

// ---------------- launch ----------------
extern "C" void kernel_launch(void* const* d_in, const int* in_sizes, int n_in,
                              void* d_out, int out_size) {
    (void)in_sizes; (void)n_in; (void)out_size;
    const float* q  = (const float*)d_in[0];
    const float* k  = (const float*)d_in[1];
    const float* v  = (const float*)d_in[2];
    const float* wk = (const float*)d_in[3];
    const float* bk = (const float*)d_in[4];
    const float* wq = (const float*)d_in[5];
    const float* bq = (const float*)d_in[6];
    const float* wv = (const float*)d_in[7];
    const float* bv = (const float*)d_in[8];
    const float* wo = (const float*)d_in[9];
    const float* bo = (const float*)d_in[10];
    float* out = (float*)d_out;

    static int smem_set = 0;
    if (!smem_set) {
        cudaFuncSetAttribute(conv_mma, cudaFuncAttributeMaxDynamicSharedMemorySize, SMEM_BYTES);
        smem_set = 1;
    }

    setup_tables<<<1, 256>>>(wo);
    cvt_inputs<<<(NB_ * SP_ * D_) / (256 * 4), 256>>>(q, k, v);
    wt_prep<<<dim3(14400, 3), 256>>>(wk, wq, wv);

    dim3 cgrid(2, 64, 3);
    // Phase 1: t0=relu(conv(k,wk)+bk), t1=relu(conv(q,wq)+bq), t2=relu(conv(v,wv)+bv)
    conv_mma<<<cgrid, 256, SMEM_BYTES>>>(1, 0, 2,
                                         0, 1, 2,
                                         bk, bq, bv,
                                         0, 1, 2, 1);
    // Phase 2: kh=conv(t0,wk)+bk, qh=conv(t1,wk)+bk (weight-sharing quirk), vh=conv(t2,wv)+bv
    conv_mma<<<cgrid, 256, SMEM_BYTES>>>(3, 4, 5,
                                         0, 0, 2,
                                         bk, bk, bv,
                                         1, 0, 2, 0);

    attn_kernel<<<NB_ * 8, 256>>>();
    out_gemm<<<dim3(4, 64), 256>>>(bo, out);
}

// round 6
// speedup vs baseline: 2.1478x; 1.1129x over previous
#include <cuda_runtime.h>
#include <cuda_fp16.h>
#include <cstdint>

#define D_   256
#define SP_  64
#define NB_  128
#define NSL_ 65

// ---------------- device scratch ----------------
__device__ __half g_wth[3][NSL_][D_][D_]; // [w][slice][o][i]  fp16 weights (B operand rows = o, k contig)
__device__ __half g_xh[3][NB_ * SP_ * D_]; // staged inputs: [0]=q, [1]=k, [2]=v (half)
__device__ __half g_th[3][NB_ * SP_ * D_]; // branch hidden (half)
__device__ float g_wot[D_ * D_];
__device__ float g_qh[NB_ * SP_ * D_];
__device__ float g_kh[NB_ * SP_ * D_];
__device__ float g_vh[NB_ * SP_ * D_];
__device__ float g_att[NB_ * SP_ * D_];
__device__ int   g_slice_of_k[225];
__device__ int   g_ps[SP_][40];
__device__ int   g_pd[SP_][40];
__device__ int   g_pcnt[SP_];

__device__ __forceinline__ bool mask_keep(int r, int c) {
    int a = min(r, 14 - r);
    int b = min(c, 14 - c);
    return (a == 7) || (b == 7) || (a >= 5 && b >= 5) || (a == b);
}

__device__ __forceinline__ float* fsel(int s) {
    switch (s) {
        case 0: return g_qh;
        case 1: return g_kh;
        default: return g_vh;
    }
}

// ---------------- PTX helpers ----------------
__device__ __forceinline__ uint32_t smem_u32(const void* p) {
    uint32_t a;
    asm("{ .reg .u64 t; cvta.to.shared.u64 t, %1; cvt.u32.u64 %0, t; }" : "=r"(a) : "l"(p));
    return a;
}
__device__ __forceinline__ void cp16(uint32_t dst, const void* src) {
    asm volatile("cp.async.cg.shared.global [%0], [%1], 16;" :: "r"(dst), "l"(src));
}
__device__ __forceinline__ void cp_commit() {
    asm volatile("cp.async.commit_group;" ::: "memory");
}
template <int N>
__device__ __forceinline__ void cp_wait() {
    asm volatile("cp.async.wait_group %0;" :: "n"(N) : "memory");
}
#define LDSM_X4(r0, r1, r2, r3, addr) \
    asm volatile("ldmatrix.sync.aligned.m8n8.x4.shared.b16 {%0,%1,%2,%3}, [%4];" \
        : "=r"(r0), "=r"(r1), "=r"(r2), "=r"(r3) : "r"(addr))
__device__ __forceinline__ void mma_f16(float& c0, float& c1, float& c2, float& c3,
                                        uint32_t a0, uint32_t a1, uint32_t a2, uint32_t a3,
                                        uint32_t b0, uint32_t b1) {
    asm volatile(
        "mma.sync.aligned.m16n8k16.row.col.f32.f16.f16.f32 "
        "{%0,%1,%2,%3}, {%4,%5,%6,%7}, {%8,%9}, {%0,%1,%2,%3};"
        : "+f"(c0), "+f"(c1), "+f"(c2), "+f"(c3)
        : "r"(a0), "r"(a1), "r"(a2), "r"(a3), "r"(b0), "r"(b1));
}

// ---------------- setup ----------------
__global__ void setup_tables(const float* __restrict__ wo) {
    int t = threadIdx.x;
    if (t == 0) {
        int cnt = 0;
        for (int kk = 0; kk < 225; kk++)
            g_slice_of_k[kk] = mask_keep(kk / 15, kk % 15) ? cnt++ : -1;
    }
    __syncthreads();
    if (t < 64) {
        int py = t >> 3, px = t & 7;
        int c = 0;
        for (int s = 0; s < 64; s++) {
            int sy = s >> 3, sx = s & 7;
            int sl = g_slice_of_k[(sy - py + 7) * 15 + (sx - px + 7)];
            if (sl >= 0) { g_ps[t][c] = s; g_pd[t][c] = sl; c++; }
        }
        g_pcnt[t] = c;
    }
    for (int idx = t; idx < D_ * D_; idx += blockDim.x) {
        int o = idx >> 8, cc = idx & 255;
        g_wot[cc * D_ + o] = wo[o * D_ + cc];
    }
}

__global__ void cvt_inputs(const float* __restrict__ q,
                           const float* __restrict__ k,
                           const float* __restrict__ v) {
    size_t i = ((size_t)blockIdx.x * blockDim.x + threadIdx.x) * 4;
    float4 a = *(const float4*)(q + i);
    float4 b = *(const float4*)(k + i);
    float4 c = *(const float4*)(v + i);
    *(__half2*)(&g_xh[0][i])     = __floats2half2_rn(a.x, a.y);
    *(__half2*)(&g_xh[0][i + 2]) = __floats2half2_rn(a.z, a.w);
    *(__half2*)(&g_xh[1][i])     = __floats2half2_rn(b.x, b.y);
    *(__half2*)(&g_xh[1][i + 2]) = __floats2half2_rn(b.z, b.w);
    *(__half2*)(&g_xh[2][i])     = __floats2half2_rn(c.x, c.y);
    *(__half2*)(&g_xh[2][i + 2]) = __floats2half2_rn(c.z, c.w);
}

__global__ void wt_prep(const float* __restrict__ wk,
                        const float* __restrict__ wq,
                        const float* __restrict__ wv) {
    int w = blockIdx.y;
    const float* src = (w == 0) ? wk : ((w == 1) ? wq : wv);
    size_t base = ((size_t)blockIdx.x * 256 + threadIdx.x) * 4;
    float4 v = *(const float4*)(src + base);
    float vv[4] = {v.x, v.y, v.z, v.w};
#pragma unroll
    for (int e = 0; e < 4; e++) {
        size_t idx = base + e;
        int kk = (int)(idx % 225);
        int oi = (int)(idx / 225);
        int i = oi & 255, o = oi >> 8;
        int sl = g_slice_of_k[kk];
        if (sl >= 0) g_wth[w][sl][o][i] = __float2half_rn(vv[e]);
    }
}

// ---------------- conv as fp16 mma.sync GEMM (ldmatrix, 3 CTAs/SM) ----------------
// grid = (4 n-tiles, 64 p, 3 branches) = 768 CTAs. CTA: M=128 x N=64, K-chunk=32.
#define PADK 40
#define A_STG_H (128 * PADK)          /* halves */
#define B_STG_H (64 * PADK)
#define NST 4
#define SMEM_BYTES (NST * (A_STG_H + B_STG_H) * 2)   /* 61440 */

__global__ void __launch_bounds__(256, 3) conv_mma(
    int xa, int xb, int xc,           // 0-2: g_xh, 3-5: g_th
    int wa, int wb, int wc,
    const float* ba, const float* bb, const float* bc,
    int ya, int yb, int yc,
    int outHalf)                      // also = doRelu
{
    extern __shared__ __half smh[];
    __half* As = smh;                           // [NST][128][PADK]
    __half* Bs = smh + NST * A_STG_H;           // [NST][64][PADK]
    __shared__ int s_ps[40], s_pd[40];

    int tid = threadIdx.x, wid = tid >> 5, lane = tid & 31;
    int o0 = blockIdx.x << 6;
    int p  = blockIdx.y;
    int br = blockIdx.z;

    int xsel, widx, ysel;
    const float* bias;
    if (br == 0)      { xsel = xa; widx = wa; bias = ba; ysel = ya; }
    else if (br == 1) { xsel = xb; widx = wb; bias = bb; ysel = yb; }
    else              { xsel = xc; widx = wc; bias = bc; ysel = yc; }
    const __half* X = (xsel < 3) ? g_xh[xsel] : g_th[xsel - 3];
    const __half* WTh = &g_wth[widx][0][0][0];

    int cnt = g_pcnt[p];
    if (tid < cnt) { s_ps[tid] = g_ps[p][tid]; s_pd[tid] = g_pd[p][tid]; }
    __syncthreads();
    int NC = cnt * 8;

    uint32_t as_base = smem_u32(As);
    uint32_t bs_base = smem_u32(Bs);

    // warp tiling: 4 (m) x 2 (n); warp tile M32 x N32
    int wm = wid & 3, wn = wid >> 2;
    int m_base = wm * 32, n_base = wn * 32;
    int g = lane >> 2, t = lane & 3;
    int quad = lane >> 3, r = lane & 7;

    // ldmatrix per-thread address offsets (bytes, within a stage)
    // A x4: mat0=(m0-7,k0-7) mat1=(m8-15,k0-7) mat2=(m0-7,k8-15) mat3=(m8-15,k8-15)
    uint32_t a_lm = (uint32_t)(((quad & 1) * 8 + r) * PADK + (quad >> 1) * 8) * 2;
    // B x4: mat0=(n0-7,k0-7) mat1=(n0-7,k8-15) mat2=(n8-15,k0-7) mat3=(n8-15,k8-15)
    uint32_t b_lm = (uint32_t)(((quad >> 1) * 8 + r) * PADK + (quad & 1) * 8) * 2;

    float acc[2][4][4];
#pragma unroll
    for (int mi = 0; mi < 2; mi++)
#pragma unroll
        for (int ni = 0; ni < 4; ni++)
#pragma unroll
            for (int e = 0; e < 4; e++) acc[mi][ni][e] = 0.f;

    auto issue = [&](int n) {
        int buf = n & 3;
        int si = n >> 3;
        int s  = s_ps[si];
        int sl = s_pd[si];
        int i0 = (n & 7) * 32;
        // A: 128 rows x 32 halves = 512 cp16 -> 2 per thread
#pragma unroll
        for (int e = 0; e < 2; e++) {
            int c = tid + (e << 8);
            int row = c >> 2, part = c & 3;
            cp16(as_base + (uint32_t)(buf * A_STG_H + row * PADK) * 2 + part * 16,
                 X + ((size_t)(row * SP_ + s) * D_ + i0 + part * 8));
        }
        // B: 64 rows x 32 halves = 256 cp16 -> 1 per thread
        {
            int row = tid >> 2, part = tid & 3;
            cp16(bs_base + (uint32_t)(buf * B_STG_H + row * PADK) * 2 + part * 16,
                 WTh + ((size_t)sl * (D_ * D_) + (size_t)(o0 + row) * D_ + i0 + part * 8));
        }
        cp_commit();
    };

    issue(0); issue(1); issue(2);

#pragma unroll 1
    for (int n = 0; n < NC; n++) {
        if (n + 3 <= NC)      cp_wait<2>();
        else if (n + 2 == NC) cp_wait<1>();
        else                  cp_wait<0>();
        __syncthreads();
        if (n + 3 < NC) issue(n + 3);

        uint32_t aS = as_base + (uint32_t)((n & 3) * A_STG_H) * 2 + (uint32_t)(m_base * PADK) * 2 + a_lm;
        uint32_t bS = bs_base + (uint32_t)((n & 3) * B_STG_H) * 2 + (uint32_t)(n_base * PADK) * 2 + b_lm;
#pragma unroll
        for (int ks = 0; ks < 2; ks++) {
            uint32_t koff = (uint32_t)(ks * 16 * 2);
            uint32_t af[2][4];
#pragma unroll
            for (int mi = 0; mi < 2; mi++)
                LDSM_X4(af[mi][0], af[mi][1], af[mi][2], af[mi][3],
                        aS + (uint32_t)(mi * 16 * PADK) * 2 + koff);
            uint32_t bf[4][2];
#pragma unroll
            for (int nj = 0; nj < 2; nj++) {
                uint32_t r0, r1, r2, r3;
                LDSM_X4(r0, r1, r2, r3, bS + (uint32_t)(nj * 16 * PADK) * 2 + koff);
                bf[nj * 2][0] = r0;     bf[nj * 2][1] = r1;
                bf[nj * 2 + 1][0] = r2; bf[nj * 2 + 1][1] = r3;
            }
#pragma unroll
            for (int mi = 0; mi < 2; mi++)
#pragma unroll
                for (int ni = 0; ni < 4; ni++)
                    mma_f16(acc[mi][ni][0], acc[mi][ni][1], acc[mi][ni][2], acc[mi][ni][3],
                            af[mi][0], af[mi][1], af[mi][2], af[mi][3],
                            bf[ni][0], bf[ni][1]);
        }
    }

    // epilogue: c0=(g,2t) c1=(g,2t+1) c2=(g+8,2t) c3=(g+8,2t+1)
    if (outHalf) {
        __half* Y = g_th[ysel];
#pragma unroll
        for (int mi = 0; mi < 2; mi++) {
#pragma unroll
            for (int ni = 0; ni < 4; ni++) {
                int m  = m_base + mi * 16 + g;
                int nn = o0 + n_base + ni * 8 + 2 * t;
                float b0 = bias[nn], b1 = bias[nn + 1];
                float v0 = fmaxf(acc[mi][ni][0] + b0, 0.f);
                float v1 = fmaxf(acc[mi][ni][1] + b1, 0.f);
                float v2 = fmaxf(acc[mi][ni][2] + b0, 0.f);
                float v3 = fmaxf(acc[mi][ni][3] + b1, 0.f);
                *(__half2*)(Y + ((size_t)(m * SP_ + p) * D_ + nn))       = __floats2half2_rn(v0, v1);
                *(__half2*)(Y + ((size_t)((m + 8) * SP_ + p) * D_ + nn)) = __floats2half2_rn(v2, v3);
            }
        }
    } else {
        float* Y = fsel(ysel);
#pragma unroll
        for (int mi = 0; mi < 2; mi++) {
#pragma unroll
            for (int ni = 0; ni < 4; ni++) {
                int m  = m_base + mi * 16 + g;
                int nn = o0 + n_base + ni * 8 + 2 * t;
                float b0 = bias[nn], b1 = bias[nn + 1];
                *(float2*)(Y + ((size_t)(m * SP_ + p) * D_ + nn)) =
                    make_float2(acc[mi][ni][0] + b0, acc[mi][ni][1] + b1);
                *(float2*)(Y + ((size_t)((m + 8) * SP_ + p) * D_ + nn)) =
                    make_float2(acc[mi][ni][2] + b0, acc[mi][ni][3] + b1);
            }
        }
    }
}

// ---------------- attention ----------------
__global__ void __launch_bounds__(256) attn_kernel() {
    __shared__ float sq[64][33];
    __shared__ float sk[64][33];
    __shared__ float sv[64][33];
    __shared__ float sc[64][64];
    int b = blockIdx.x >> 3, h = blockIdx.x & 7;
    int tid = threadIdx.x;
    const float* qb = g_qh + (size_t)b * (SP_ * D_) + h * 32;
    const float* kb = g_kh + (size_t)b * (SP_ * D_) + h * 32;
    const float* vb = g_vh + (size_t)b * (SP_ * D_) + h * 32;
#pragma unroll
    for (int e = 0; e < 8; e++) {
        int idx = tid + e * 256;
        int pp = idx >> 5, dk = idx & 31;
        sq[pp][dk] = qb[pp * D_ + dk];
        sk[pp][dk] = kb[pp * D_ + dk];
        sv[pp][dk] = vb[pp * D_ + dk];
    }
    __syncthreads();
    int lane = tid & 31, w = tid >> 5;
    const float scale = 0.17677669529663687f;
#pragma unroll 1
    for (int r = 0; r < 8; r++) {
        int i = w * 8 + r;
        float a0 = 0.f, a1 = 0.f;
#pragma unroll
        for (int dk = 0; dk < 32; dk++) {
            float qv = sq[i][dk];
            a0 = fmaf(qv, sk[lane][dk], a0);
            a1 = fmaf(qv, sk[lane + 32][dk], a1);
        }
        a0 *= scale; a1 *= scale;
        float mx = fmaxf(a0, a1);
#pragma unroll
        for (int off = 16; off; off >>= 1) mx = fmaxf(mx, __shfl_xor_sync(0xffffffffu, mx, off));
        float e0 = __expf(a0 - mx), e1 = __expf(a1 - mx);
        float sm = e0 + e1;
#pragma unroll
        for (int off = 16; off; off >>= 1) sm += __shfl_xor_sync(0xffffffffu, sm, off);
        float inv = 1.0f / sm;
        sc[i][lane] = e0 * inv;
        sc[i][lane + 32] = e1 * inv;
    }
    __syncthreads();
    float o[8];
#pragma unroll
    for (int r = 0; r < 8; r++) o[r] = 0.f;
#pragma unroll 1
    for (int j = 0; j < 64; j++) {
        float vv = sv[j][lane];
#pragma unroll
        for (int r = 0; r < 8; r++) o[r] = fmaf(sc[w * 8 + r][j], vv, o[r]);
    }
    float* ob = g_att + (size_t)b * (SP_ * D_) + h * 32 + lane;
#pragma unroll
    for (int r = 0; r < 8; r++) ob[(size_t)(w * 8 + r) * D_] = o[r];
}

// ---------------- output projection ----------------
__global__ void __launch_bounds__(256) out_gemm(const float* __restrict__ bo, float* __restrict__ Y) {
    __shared__ float As2[8][132];
    __shared__ float Bs2[8][68];
    int o0   = blockIdx.x << 6;
    int row0 = blockIdx.y << 7;
    int tid = threadIdx.x;
    int tx = tid & 15, ty = tid >> 4;
    float acc[8][4];
#pragma unroll
    for (int r = 0; r < 8; r++)
#pragma unroll
        for (int c = 0; c < 4; c++) acc[r][c] = 0.f;
    int am = tid >> 1, akb = (tid & 1) * 4;
    const float* A = g_att + (size_t)(row0 + am) * D_ + akb;
#pragma unroll 1
    for (int i0 = 0; i0 < D_; i0 += 8) {
        float4 va = *(const float4*)(A + i0);
        As2[akb + 0][am] = va.x; As2[akb + 1][am] = va.y;
        As2[akb + 2][am] = va.z; As2[akb + 3][am] = va.w;
#pragma unroll
        for (int e = 0; e < 2; e++) {
            int idx = tid + e * 256;
            int kq = idx >> 6, nn = idx & 63;
            Bs2[kq][nn] = g_wot[(size_t)(i0 + kq) * D_ + o0 + nn];
        }
        __syncthreads();
#pragma unroll
        for (int kk = 0; kk < 8; kk++) {
            float a[8], b4[4];
            *(float4*)(a)     = *(const float4*)&As2[kk][ty * 4];
            *(float4*)(a + 4) = *(const float4*)&As2[kk][64 + ty * 4];
            *(float4*)(b4)    = *(const float4*)&Bs2[kk][tx * 4];
#pragma unroll
            for (int r = 0; r < 8; r++)
#pragma unroll
                for (int c = 0; c < 4; c++)
                    acc[r][c] = fmaf(a[r], b4[c], acc[r][c]);
        }
        __syncthreads();
    }
#pragma unroll
    for (int r = 0; r < 8; r++) {
        int m = (r < 4) ? (ty * 4 + r) : (64 + ty * 4 + r - 4);
        float* yrow = Y + (size_t)(row0 + m) * D_ + o0;
#pragma unroll
        for (int c = 0; c < 4; c++) {
            int nn = tx * 4 + c;
            yrow[nn] = acc[r][c] + bo[o0 + nn];
        }
    }
}

// ---------------- launch ----------------
extern "C" void kernel_launch(void* const* d_in, const int* in_sizes, int n_in,
                              void* d_out, int out_size) {
    (void)in_sizes; (void)n_in; (void)out_size;
    const float* q  = (const float*)d_in[0];
    const float* k  = (const float*)d_in[1];
    const float* v  = (const float*)d_in[2];
    const float* wk = (const float*)d_in[3];
    const float* bk = (const float*)d_in[4];
    const float* wq = (const float*)d_in[5];
    const float* bq = (const float*)d_in[6];
    const float* wv = (const float*)d_in[7];
    const float* bv = (const float*)d_in[8];
    const float* wo = (const float*)d_in[9];
    const float* bo = (const float*)d_in[10];
    float* out = (float*)d_out;

    static int smem_set = 0;
    if (!smem_set) {
        cudaFuncSetAttribute(conv_mma, cudaFuncAttributeMaxDynamicSharedMemorySize, SMEM_BYTES);
        smem_set = 1;
    }

    setup_tables<<<1, 256>>>(wo);
    cvt_inputs<<<(NB_ * SP_ * D_) / (256 * 4), 256>>>(q, k, v);
    wt_prep<<<dim3(14400, 3), 256>>>(wk, wq, wv);

    dim3 cgrid(4, 64, 3);
    // Phase 1: t0=relu(conv(k,wk)+bk), t1=relu(conv(q,wq)+bq), t2=relu(conv(v,wv)+bv)
    conv_mma<<<cgrid, 256, SMEM_BYTES>>>(1, 0, 2,
                                         0, 1, 2,
                                         bk, bq, bv,
                                         0, 1, 2, 1);
    // Phase 2: kh=conv(t0,wk)+bk, qh=conv(t1,wk)+bk (weight-sharing quirk), vh=conv(t2,wv)+bv
    conv_mma<<<cgrid, 256, SMEM_BYTES>>>(3, 4, 5,
                                         0, 0, 2,
                                         bk, bk, bv,
                                         1, 0, 2, 0);

    attn_kernel<<<NB_ * 8, 256>>>();
    out_gemm<<<dim3(4, 64), 256>>>(bo, out);
}

// round 7
// speedup vs baseline: 2.8606x; 1.3319x over previous
#include <cuda_runtime.h>
#include <cuda_fp16.h>
#include <cstdint>

#define D_   256
#define SP_  64
#define NB_  128
#define NSL_ 65

// ---------------- device scratch ----------------
__device__ __half g_wth[3][NSL_][D_][D_]; // [w][slice][o][i]  fp16 weights
__device__ __half g_xh[3][NB_ * SP_ * D_]; // staged inputs: [0]=q, [1]=k, [2]=v
__device__ __half g_th[3][NB_ * SP_ * D_]; // branch hidden
__device__ float g_wot[D_ * D_];
__device__ float g_qh[NB_ * SP_ * D_];
__device__ float g_kh[NB_ * SP_ * D_];
__device__ float g_vh[NB_ * SP_ * D_];
__device__ float g_att[NB_ * SP_ * D_];
__device__ int   g_slice_of_k[225];
__device__ int   g_ps[SP_][40];
__device__ int   g_pd[SP_][40];
__device__ int   g_pcnt[SP_];

__device__ __forceinline__ bool mask_keep(int r, int c) {
    int a = min(r, 14 - r);
    int b = min(c, 14 - c);
    return (a == 7) || (b == 7) || (a >= 5 && b >= 5) || (a == b);
}

__device__ __forceinline__ float* fsel(int s) {
    switch (s) {
        case 0: return g_qh;
        case 1: return g_kh;
        default: return g_vh;
    }
}

// ---------------- PTX helpers ----------------
__device__ __forceinline__ uint32_t smem_u32(const void* p) {
    uint32_t a;
    asm("{ .reg .u64 t; cvta.to.shared.u64 t, %1; cvt.u32.u64 %0, t; }" : "=r"(a) : "l"(p));
    return a;
}
__device__ __forceinline__ void cp16(uint32_t dst, const void* src) {
    asm volatile("cp.async.cg.shared.global [%0], [%1], 16;" :: "r"(dst), "l"(src));
}
__device__ __forceinline__ void cp_commit() {
    asm volatile("cp.async.commit_group;" ::: "memory");
}
template <int N>
__device__ __forceinline__ void cp_wait() {
    asm volatile("cp.async.wait_group %0;" :: "n"(N) : "memory");
}
#define LDSM_X4(r0, r1, r2, r3, addr) \
    asm volatile("ldmatrix.sync.aligned.m8n8.x4.shared.b16 {%0,%1,%2,%3}, [%4];" \
        : "=r"(r0), "=r"(r1), "=r"(r2), "=r"(r3) : "r"(addr))
__device__ __forceinline__ void mma_f16(float& c0, float& c1, float& c2, float& c3,
                                        uint32_t a0, uint32_t a1, uint32_t a2, uint32_t a3,
                                        uint32_t b0, uint32_t b1) {
    asm volatile(
        "mma.sync.aligned.m16n8k16.row.col.f32.f16.f16.f32 "
        "{%0,%1,%2,%3}, {%4,%5,%6,%7}, {%8,%9}, {%0,%1,%2,%3};"
        : "+f"(c0), "+f"(c1), "+f"(c2), "+f"(c3)
        : "r"(a0), "r"(a1), "r"(a2), "r"(a3), "r"(b0), "r"(b1));
}

// ---------------- setup ----------------
__global__ void setup_tables(const float* __restrict__ wo) {
    int t = threadIdx.x;
    if (blockIdx.x == 0) {
        if (t == 0) {
            int cnt = 0;
            for (int kk = 0; kk < 225; kk++)
                g_slice_of_k[kk] = mask_keep(kk / 15, kk % 15) ? cnt++ : -1;
        }
        __syncthreads();
        if (t < 64) {
            int py = t >> 3, px = t & 7;
            int c = 0;
            for (int s = 0; s < 64; s++) {
                int sy = s >> 3, sx = s & 7;
                int sl = g_slice_of_k[(sy - py + 7) * 15 + (sx - px + 7)];
                if (sl >= 0) { g_ps[t][c] = s; g_pd[t][c] = sl; c++; }
            }
            g_pcnt[t] = c;
        }
    }
    // wot transpose, split over 64 blocks
    int base = blockIdx.x * 1024;
#pragma unroll
    for (int e = 0; e < 4; e++) {
        int idx = base + t + e * 256;
        int o = idx >> 8, cc = idx & 255;
        g_wot[cc * D_ + o] = wo[o * D_ + cc];
    }
}

__global__ void cvt_inputs(const float* __restrict__ q,
                           const float* __restrict__ k,
                           const float* __restrict__ v) {
    size_t i = ((size_t)blockIdx.x * blockDim.x + threadIdx.x) * 4;
    float4 a = *(const float4*)(q + i);
    float4 b = *(const float4*)(k + i);
    float4 c = *(const float4*)(v + i);
    *(__half2*)(&g_xh[0][i])     = __floats2half2_rn(a.x, a.y);
    *(__half2*)(&g_xh[0][i + 2]) = __floats2half2_rn(a.z, a.w);
    *(__half2*)(&g_xh[1][i])     = __floats2half2_rn(b.x, b.y);
    *(__half2*)(&g_xh[1][i + 2]) = __floats2half2_rn(b.z, b.w);
    *(__half2*)(&g_xh[2][i])     = __floats2half2_rn(c.x, c.y);
    *(__half2*)(&g_xh[2][i + 2]) = __floats2half2_rn(c.z, c.w);
}

// weight repack: block=(o, w), thread=i. Per-thread reads contiguous 225-float
// row (L1 resident), warp writes 64B-coalesced half rows per active tap.
__global__ void wt_prep(const float* __restrict__ wk,
                        const float* __restrict__ wq,
                        const float* __restrict__ wv) {
    __shared__ int ssl[225];
    int w = blockIdx.y;
    int o = blockIdx.x;
    const float* src = (w == 0) ? wk : ((w == 1) ? wq : wv);
    int i = threadIdx.x;
    if (i < 225) ssl[i] = g_slice_of_k[i];
    __syncthreads();
    const float* row = src + ((size_t)o * D_ + i) * 225;
    __half* dst = &g_wth[w][0][o][i];
#pragma unroll 1
    for (int kk = 0; kk < 225; kk++) {
        int sl = ssl[kk];
        float v = row[kk];
        if (sl >= 0) dst[(size_t)sl * (D_ * D_)] = __float2half_rn(v);
    }
}

// ---------------- conv as fp16 mma.sync GEMM ----------------
// grid = (4 n-tiles, 64 p, 3 branches) = 768 CTAs. CTA: M=128 x N=64, K-chunk=64.
// 2-stage cp.async ring, 3 CTAs/SM, ldmatrix feeds.
#define PADK 72
#define A_STG_H (128 * PADK)          /* halves */
#define B_STG_H (64 * PADK)
#define NST 2
#define SMEM_BYTES (NST * (A_STG_H + B_STG_H) * 2)   /* 55296 */

__global__ void __launch_bounds__(256, 3) conv_mma(
    int xa, int xb, int xc,           // 0-2: g_xh, 3-5: g_th
    int wa, int wb, int wc,
    const float* ba, const float* bb, const float* bc,
    int ya, int yb, int yc,
    int outHalf)                      // also = doRelu
{
    extern __shared__ __half smh[];
    __half* As = smh;                           // [NST][128][PADK]
    __half* Bs = smh + NST * A_STG_H;           // [NST][64][PADK]
    __shared__ int s_ps[40], s_pd[40];

    int tid = threadIdx.x, wid = tid >> 5, lane = tid & 31;
    int o0 = blockIdx.x << 6;
    int p  = blockIdx.y;
    int br = blockIdx.z;

    int xsel, widx, ysel;
    const float* bias;
    if (br == 0)      { xsel = xa; widx = wa; bias = ba; ysel = ya; }
    else if (br == 1) { xsel = xb; widx = wb; bias = bb; ysel = yb; }
    else              { xsel = xc; widx = wc; bias = bc; ysel = yc; }
    const __half* X = (xsel < 3) ? g_xh[xsel] : g_th[xsel - 3];
    const __half* WTh = &g_wth[widx][0][0][0];

    int cnt = g_pcnt[p];
    if (tid < cnt) { s_ps[tid] = g_ps[p][tid]; s_pd[tid] = g_pd[p][tid]; }
    __syncthreads();
    int NC = cnt * 4;                 // 64-wide K chunks

    uint32_t as_base = smem_u32(As);
    uint32_t bs_base = smem_u32(Bs);

    // warp tiling: 4 (m) x 2 (n); warp tile M32 x N32
    int wm = wid & 3, wn = wid >> 2;
    int m_base = wm * 32, n_base = wn * 32;
    int g = lane >> 2, t = lane & 3;
    int quad = lane >> 3, r = lane & 7;

    uint32_t a_lm = (uint32_t)(((quad & 1) * 8 + r) * PADK + (quad >> 1) * 8) * 2;
    uint32_t b_lm = (uint32_t)(((quad >> 1) * 8 + r) * PADK + (quad & 1) * 8) * 2;

    float acc[2][4][4];
#pragma unroll
    for (int mi = 0; mi < 2; mi++)
#pragma unroll
        for (int ni = 0; ni < 4; ni++)
#pragma unroll
            for (int e = 0; e < 4; e++) acc[mi][ni][e] = 0.f;

    auto issue = [&](int n) {
        int buf = n & 1;
        int si = n >> 2;
        int s  = s_ps[si];
        int sl = s_pd[si];
        int i0 = (n & 3) * 64;
        // A: 128 rows x 64 halves = 8 parts/row -> 1024 cp16 -> 4/thread
#pragma unroll
        for (int e = 0; e < 4; e++) {
            int c = tid + (e << 8);
            int row = c >> 3, part = c & 7;
            cp16(as_base + (uint32_t)(buf * A_STG_H + row * PADK + part * 8) * 2,
                 X + ((size_t)(row * SP_ + s) * D_ + i0 + part * 8));
        }
        // B: 64 rows x 64 halves -> 512 cp16 -> 2/thread
#pragma unroll
        for (int e = 0; e < 2; e++) {
            int c = tid + (e << 8);
            int row = c >> 3, part = c & 7;
            cp16(bs_base + (uint32_t)(buf * B_STG_H + row * PADK + part * 8) * 2,
                 WTh + ((size_t)sl * (D_ * D_) + (size_t)(o0 + row) * D_ + i0 + part * 8));
        }
        cp_commit();
    };

    issue(0);

#pragma unroll 1
    for (int n = 0; n < NC; n++) {
        cp_wait<0>();
        __syncthreads();
        if (n + 1 < NC) issue(n + 1);   // overlaps with compute(n) below

        uint32_t aS = as_base + (uint32_t)((n & 1) * A_STG_H + m_base * PADK) * 2 + a_lm;
        uint32_t bS = bs_base + (uint32_t)((n & 1) * B_STG_H + n_base * PADK) * 2 + b_lm;
#pragma unroll
        for (int ks = 0; ks < 4; ks++) {
            uint32_t koff = (uint32_t)(ks * 16 * 2);
            uint32_t af[2][4];
#pragma unroll
            for (int mi = 0; mi < 2; mi++)
                LDSM_X4(af[mi][0], af[mi][1], af[mi][2], af[mi][3],
                        aS + (uint32_t)(mi * 16 * PADK) * 2 + koff);
            uint32_t bf[4][2];
#pragma unroll
            for (int nj = 0; nj < 2; nj++) {
                uint32_t r0, r1, r2, r3;
                LDSM_X4(r0, r1, r2, r3, bS + (uint32_t)(nj * 16 * PADK) * 2 + koff);
                bf[nj * 2][0] = r0;     bf[nj * 2][1] = r1;
                bf[nj * 2 + 1][0] = r2; bf[nj * 2 + 1][1] = r3;
            }
#pragma unroll
            for (int mi = 0; mi < 2; mi++)
#pragma unroll
                for (int ni = 0; ni < 4; ni++)
                    mma_f16(acc[mi][ni][0], acc[mi][ni][1], acc[mi][ni][2], acc[mi][ni][3],
                            af[mi][0], af[mi][1], af[mi][2], af[mi][3],
                            bf[ni][0], bf[ni][1]);
        }
    }

    // epilogue: c0=(g,2t) c1=(g,2t+1) c2=(g+8,2t) c3=(g+8,2t+1)
    if (outHalf) {
        __half* Y = g_th[ysel];
#pragma unroll
        for (int mi = 0; mi < 2; mi++) {
#pragma unroll
            for (int ni = 0; ni < 4; ni++) {
                int m  = m_base + mi * 16 + g;
                int nn = o0 + n_base + ni * 8 + 2 * t;
                float b0 = bias[nn], b1 = bias[nn + 1];
                float v0 = fmaxf(acc[mi][ni][0] + b0, 0.f);
                float v1 = fmaxf(acc[mi][ni][1] + b1, 0.f);
                float v2 = fmaxf(acc[mi][ni][2] + b0, 0.f);
                float v3 = fmaxf(acc[mi][ni][3] + b1, 0.f);
                *(__half2*)(Y + ((size_t)(m * SP_ + p) * D_ + nn))       = __floats2half2_rn(v0, v1);
                *(__half2*)(Y + ((size_t)((m + 8) * SP_ + p) * D_ + nn)) = __floats2half2_rn(v2, v3);
            }
        }
    } else {
        float* Y = fsel(ysel);
#pragma unroll
        for (int mi = 0; mi < 2; mi++) {
#pragma unroll
            for (int ni = 0; ni < 4; ni++) {
                int m  = m_base + mi * 16 + g;
                int nn = o0 + n_base + ni * 8 + 2 * t;
                float b0 = bias[nn], b1 = bias[nn + 1];
                *(float2*)(Y + ((size_t)(m * SP_ + p) * D_ + nn)) =
                    make_float2(acc[mi][ni][0] + b0, acc[mi][ni][1] + b1);
                *(float2*)(Y + ((size_t)((m + 8) * SP_ + p) * D_ + nn)) =
                    make_float2(acc[mi][ni][2] + b0, acc[mi][ni][3] + b1);
            }
        }
    }
}

// ---------------- attention ----------------
__global__ void __launch_bounds__(256) attn_kernel() {
    __shared__ float sq[64][33];
    __shared__ float sk[64][33];
    __shared__ float sv[64][33];
    __shared__ float sc[64][64];
    int b = blockIdx.x >> 3, h = blockIdx.x & 7;
    int tid = threadIdx.x;
    const float* qb = g_qh + (size_t)b * (SP_ * D_) + h * 32;
    const float* kb = g_kh + (size_t)b * (SP_ * D_) + h * 32;
    const float* vb = g_vh + (size_t)b * (SP_ * D_) + h * 32;
#pragma unroll
    for (int e = 0; e < 8; e++) {
        int idx = tid + e * 256;
        int pp = idx >> 5, dk = idx & 31;
        sq[pp][dk] = qb[pp * D_ + dk];
        sk[pp][dk] = kb[pp * D_ + dk];
        sv[pp][dk] = vb[pp * D_ + dk];
    }
    __syncthreads();
    int lane = tid & 31, w = tid >> 5;
    const float scale = 0.17677669529663687f;
#pragma unroll 1
    for (int r = 0; r < 8; r++) {
        int i = w * 8 + r;
        float a0 = 0.f, a1 = 0.f;
#pragma unroll
        for (int dk = 0; dk < 32; dk++) {
            float qv = sq[i][dk];
            a0 = fmaf(qv, sk[lane][dk], a0);
            a1 = fmaf(qv, sk[lane + 32][dk], a1);
        }
        a0 *= scale; a1 *= scale;
        float mx = fmaxf(a0, a1);
#pragma unroll
        for (int off = 16; off; off >>= 1) mx = fmaxf(mx, __shfl_xor_sync(0xffffffffu, mx, off));
        float e0 = __expf(a0 - mx), e1 = __expf(a1 - mx);
        float sm = e0 + e1;
#pragma unroll
        for (int off = 16; off; off >>= 1) sm += __shfl_xor_sync(0xffffffffu, sm, off);
        float inv = 1.0f / sm;
        sc[i][lane] = e0 * inv;
        sc[i][lane + 32] = e1 * inv;
    }
    __syncthreads();
    float o[8];
#pragma unroll
    for (int r = 0; r < 8; r++) o[r] = 0.f;
#pragma unroll 1
    for (int j = 0; j < 64; j++) {
        float vv = sv[j][lane];
#pragma unroll
        for (int r = 0; r < 8; r++) o[r] = fmaf(sc[w * 8 + r][j], vv, o[r]);
    }
    float* ob = g_att + (size_t)b * (SP_ * D_) + h * 32 + lane;
#pragma unroll
    for (int r = 0; r < 8; r++) ob[(size_t)(w * 8 + r) * D_] = o[r];
}

// ---------------- output projection ----------------
__global__ void __launch_bounds__(256) out_gemm(const float* __restrict__ bo, float* __restrict__ Y) {
    __shared__ float As2[8][132];
    __shared__ float Bs2[8][68];
    int o0   = blockIdx.x << 6;
    int row0 = blockIdx.y << 7;
    int tid = threadIdx.x;
    int tx = tid & 15, ty = tid >> 4;
    float acc[8][4];
#pragma unroll
    for (int r = 0; r < 8; r++)
#pragma unroll
        for (int c = 0; c < 4; c++) acc[r][c] = 0.f;
    int am = tid >> 1, akb = (tid & 1) * 4;
    const float* A = g_att + (size_t)(row0 + am) * D_ + akb;
#pragma unroll 1
    for (int i0 = 0; i0 < D_; i0 += 8) {
        float4 va = *(const float4*)(A + i0);
        As2[akb + 0][am] = va.x; As2[akb + 1][am] = va.y;
        As2[akb + 2][am] = va.z; As2[akb + 3][am] = va.w;
#pragma unroll
        for (int e = 0; e < 2; e++) {
            int idx = tid + e * 256;
            int kq = idx >> 6, nn = idx & 63;
            Bs2[kq][nn] = g_wot[(size_t)(i0 + kq) * D_ + o0 + nn];
        }
        __syncthreads();
#pragma unroll
        for (int kk = 0; kk < 8; kk++) {
            float a[8], b4[4];
            *(float4*)(a)     = *(const float4*)&As2[kk][ty * 4];
            *(float4*)(a + 4) = *(const float4*)&As2[kk][64 + ty * 4];
            *(float4*)(b4)    = *(const float4*)&Bs2[kk][tx * 4];
#pragma unroll
            for (int r = 0; r < 8; r++)
#pragma unroll
                for (int c = 0; c < 4; c++)
                    acc[r][c] = fmaf(a[r], b4[c], acc[r][c]);
        }
        __syncthreads();
    }
#pragma unroll
    for (int r = 0; r < 8; r++) {
        int m = (r < 4) ? (ty * 4 + r) : (64 + ty * 4 + r - 4);
        float* yrow = Y + (size_t)(row0 + m) * D_ + o0;
#pragma unroll
        for (int c = 0; c < 4; c++) {
            int nn = tx * 4 + c;
            yrow[nn] = acc[r][c] + bo[o0 + nn];
        }
    }
}

// ---------------- launch ----------------
extern "C" void kernel_launch(void* const* d_in, const int* in_sizes, int n_in,
                              void* d_out, int out_size) {
    (void)in_sizes; (void)n_in; (void)out_size;
    const float* q  = (const float*)d_in[0];
    const float* k  = (const float*)d_in[1];
    const float* v  = (const float*)d_in[2];
    const float* wk = (const float*)d_in[3];
    const float* bk = (const float*)d_in[4];
    const float* wq = (const float*)d_in[5];
    const float* bq = (const float*)d_in[6];
    const float* wv = (const float*)d_in[7];
    const float* bv = (const float*)d_in[8];
    const float* wo = (const float*)d_in[9];
    const float* bo = (const float*)d_in[10];
    float* out = (float*)d_out;

    static int smem_set = 0;
    if (!smem_set) {
        cudaFuncSetAttribute(conv_mma, cudaFuncAttributeMaxDynamicSharedMemorySize, SMEM_BYTES);
        smem_set = 1;
    }

    setup_tables<<<64, 256>>>(wo);
    cvt_inputs<<<(NB_ * SP_ * D_) / (256 * 4), 256>>>(q, k, v);
    wt_prep<<<dim3(256, 3), 256>>>(wk, wq, wv);

    dim3 cgrid(4, 64, 3);
    // Phase 1: t0=relu(conv(k,wk)+bk), t1=relu(conv(q,wq)+bq), t2=relu(conv(v,wv)+bv)
    conv_mma<<<cgrid, 256, SMEM_BYTES>>>(1, 0, 2,
                                         0, 1, 2,
                                         bk, bq, bv,
                                         0, 1, 2, 1);
    // Phase 2: kh=conv(t0,wk)+bk, qh=conv(t1,wk)+bk (weight-sharing quirk), vh=conv(t2,wv)+bv
    conv_mma<<<cgrid, 256, SMEM_BYTES>>>(3, 4, 5,
                                         0, 0, 2,
                                         bk, bk, bv,
                                         1, 0, 2, 0);

    attn_kernel<<<NB_ * 8, 256>>>();
    out_gemm<<<dim3(4, 64), 256>>>(bo, out);
}